// round 8
// baseline (speedup 1.0000x reference)
#include <cuda_runtime.h>
#include <cstdint>

// Problem constants: B=64, C=128, M=H*W=4096, fp32 in/out
#define BB 64
#define CC 128
#define MM 4096
#define KS 2                    // split-K across CTAs
#define KCHUNK (MM / KS)        // 2048
#define KTILE 32                // bf16 k per stage
#define NSTAGE (KCHUNK / KTILE) // 64
#define PITCH 80                // smem row pitch bytes (64B data + 16B pad)
#define TILEB (CC * PITCH)      // 10240 bytes per bf16 tile
#define SPITCH 72               // transpose buffer pitch (floats)
#define NTHREADS 320            // 8 consumer warps + 2 producer warps

// ---------------- scratch (__device__ globals; no allocs allowed) ----------
__device__ float g_sum[KS * BB * CC];            // per-(ks,b,c) row sums
__device__ float g_part[KS * BB * CC * CC];      // per-ks S = P + Q + Q^T

// ---------------- helpers ---------------------------------------------------
__device__ __forceinline__ uint32_t smem_u32(const void* p) {
    uint32_t a;
    asm("{ .reg .u64 t; cvta.to.shared.u64 t, %1; cvt.u32.u64 %0, t; }"
        : "=r"(a) : "l"(p));
    return a;
}
__device__ __forceinline__ void ldsm_x4(uint32_t& r0, uint32_t& r1,
                                        uint32_t& r2, uint32_t& r3, uint32_t a) {
    asm volatile("ldmatrix.sync.aligned.m8n8.x4.shared.b16 {%0,%1,%2,%3}, [%4];"
                 : "=r"(r0), "=r"(r1), "=r"(r2), "=r"(r3) : "r"(a));
}
__device__ __forceinline__ void mma_bf16(float* d, const uint32_t* a,
                                         uint32_t b0, uint32_t b1) {
    asm volatile(
        "mma.sync.aligned.m16n8k16.row.col.f32.bf16.bf16.f32 "
        "{%0,%1,%2,%3}, {%4,%5,%6,%7}, {%8,%9}, {%0,%1,%2,%3};"
        : "+f"(d[0]), "+f"(d[1]), "+f"(d[2]), "+f"(d[3])
        : "r"(a[0]), "r"(a[1]), "r"(a[2]), "r"(a[3]), "r"(b0), "r"(b1));
}
#define MBAR_INIT(a, n) \
    asm volatile("mbarrier.init.shared.b64 [%0], %1;" :: "r"(a), "r"(n) : "memory")
#define MBAR_ARRIVE(a) \
    asm volatile("mbarrier.arrive.shared.b64 _, [%0];" :: "r"(a) : "memory")
#define MBAR_WAIT(a, ph) do {                                                  \
    uint32_t _m = (a), _p = (ph), _d;                                          \
    asm volatile("{ .reg .pred p;"                                             \
        " mbarrier.try_wait.parity.acquire.cta.shared::cta.b64 p, [%1], %2;"   \
        " selp.b32 %0, 1, 0, p; }" : "=r"(_d) : "r"(_m), "r"(_p) : "memory");  \
    if (!_d) {                                                                 \
        asm volatile("{ .reg .pred P1; WL_%=:"                                 \
            " mbarrier.try_wait.parity.acquire.cta.shared::cta.b64 P1, [%0], %1, 0x989680;" \
            " @P1 bra.uni WD_%=; bra.uni WL_%=; WD_%=: }"                      \
            :: "r"(_m), "r"(_p) : "memory");                                   \
    }                                                                          \
} while (0)

// ---------------------------------------------------------------------------
// Warp-specialized SYRK: 8 consumer warps (mma), 2 producer warps
// (LDG + bf16 split + STS + row sums). grid = (KS, BB), 320 threads.
// ---------------------------------------------------------------------------
__global__ void __launch_bounds__(NTHREADS, 1) syrk_mma(const float* __restrict__ x) {
    __shared__ __align__(128) union {
        uint8_t tiles[2][2 * TILEB];        // 40960 B: hi/lo double-buffered
        float S[CC][SPITCH];                // 36864 B: Q-transpose staging
    } sm;
    __shared__ __align__(16) uint64_t mbar[4];   // full0, empty0, full1, empty1

    const int tid = threadIdx.x;
    const int wid = tid >> 5;
    const int lid = tid & 31;
    const int b = blockIdx.y;
    const int ks = blockIdx.x;
    const float* xb = x + (size_t)b * CC * MM + ks * KCHUNK;

    const uint32_t mb_full0  = smem_u32(&mbar[0]);
    const uint32_t mb_empty0 = smem_u32(&mbar[1]);
    const uint32_t mb_full1  = smem_u32(&mbar[2]);
    const uint32_t mb_empty1 = smem_u32(&mbar[3]);

    if (tid == 0) {
        MBAR_INIT(mb_full0, 64);  MBAR_INIT(mb_empty0, 8);
        MBAR_INIT(mb_full1, 64);  MBAR_INIT(mb_empty1, 8);
    }
    __syncthreads();

    const int g = lid >> 2;            // 0..7  (used by consumers)
    const int tg = lid & 3;            // 0..3

    float accP[2][8][4], accQ[2][8][4];

    if (wid < 8) {
        // ===================== CONSUMERS =====================
        const int rw = (wid >> 1) * 32;
        const int cw = (wid & 1) * 64;
        #pragma unroll
        for (int mb = 0; mb < 2; mb++)
            #pragma unroll
            for (int jb = 0; jb < 8; jb++)
                #pragma unroll
                for (int q = 0; q < 4; q++) { accP[mb][jb][q] = 0.f; accQ[mb][jb][q] = 0.f; }

        const uint32_t a_row_off = ((lid & 7) + ((lid >> 3) & 1) * 8) * PITCH
                                 + ((lid >> 4) * 8) * 2;
        const uint32_t b4_row_off = ((lid & 7) + (lid >> 4) * 8) * PITCH
                                  + (((lid >> 3) & 1) * 8) * 2;

        for (int s = 0; s < NSTAGE; s++) {
            const int buf = s & 1;
            const uint32_t mf = buf ? mb_full1 : mb_full0;
            const uint32_t me = buf ? mb_empty1 : mb_empty0;
            MBAR_WAIT(mf, (s >> 1) & 1);
            const uint32_t hibase = smem_u32(&sm.tiles[buf][0]);
            const uint32_t lobase = hibase + TILEB;

            #pragma unroll
            for (int kb = 0; kb < 2; kb++) {
                uint32_t ah[2][4];
                #pragma unroll
                for (int mb = 0; mb < 2; mb++) {
                    const uint32_t aoff = (rw + mb * 16) * PITCH + kb * 32 + a_row_off;
                    ldsm_x4(ah[mb][0], ah[mb][1], ah[mb][2], ah[mb][3], hibase + aoff);
                }
                #pragma unroll
                for (int jbp = 0; jbp < 4; jbp++) {
                    const uint32_t boff = (cw + jbp * 16) * PITCH + kb * 32 + b4_row_off;
                    uint32_t bh0, bh1, bh2, bh3, bl0, bl1, bl2, bl3;
                    ldsm_x4(bh0, bh1, bh2, bh3, hibase + boff);
                    ldsm_x4(bl0, bl1, bl2, bl3, lobase + boff);
                    #pragma unroll
                    for (int mb = 0; mb < 2; mb++) {
                        mma_bf16(accP[mb][2 * jbp + 0], ah[mb], bh0, bh1);
                        mma_bf16(accP[mb][2 * jbp + 1], ah[mb], bh2, bh3);
                        mma_bf16(accQ[mb][2 * jbp + 0], ah[mb], bl0, bl1);
                        mma_bf16(accQ[mb][2 * jbp + 1], ah[mb], bl2, bl3);
                    }
                }
            }
            __syncwarp();
            if (lid == 0) MBAR_ARRIVE(me);
        }
    } else {
        // ===================== PRODUCERS =====================
        const int pt = tid - 256;          // 0..63
        const int kseg = pt & 7;           // k segment (float4)
        const int gr = pt >> 3;            // 0..7 row group
        float rs[16];
        #pragma unroll
        for (int i = 0; i < 16; i++) rs[i] = 0.f;

        float4 v[16];
        #pragma unroll
        for (int it = 0; it < 16; it++)
            v[it] = *reinterpret_cast<const float4*>(
                xb + (size_t)(it * 8 + gr) * MM + kseg * 4);

        for (int s = 0; s < NSTAGE; s++) {
            const int buf = s & 1;
            const uint32_t mf = buf ? mb_full1 : mb_full0;
            const uint32_t me = buf ? mb_empty1 : mb_empty0;
            MBAR_WAIT(me, 1 ^ ((s >> 1) & 1));
            const uint32_t hibase = smem_u32(&sm.tiles[buf][0]);
            const uint32_t lobase = hibase + TILEB;

            #pragma unroll
            for (int it = 0; it < 16; it++) {
                const int row = it * 8 + gr;
                const float4 xv = v[it];
                rs[it] += (xv.x + xv.y) + (xv.z + xv.w);
                uint32_t h01, h23, l01, l23;
                asm("cvt.rn.bf16x2.f32 %0, %1, %2;" : "=r"(h01) : "f"(xv.y), "f"(xv.x));
                asm("cvt.rn.bf16x2.f32 %0, %1, %2;" : "=r"(h23) : "f"(xv.w), "f"(xv.z));
                const float hx = __uint_as_float(h01 << 16);
                const float hy = __uint_as_float(h01 & 0xffff0000u);
                const float hz = __uint_as_float(h23 << 16);
                const float hw = __uint_as_float(h23 & 0xffff0000u);
                asm("cvt.rn.bf16x2.f32 %0, %1, %2;" : "=r"(l01) : "f"(xv.y - hy), "f"(xv.x - hx));
                asm("cvt.rn.bf16x2.f32 %0, %1, %2;" : "=r"(l23) : "f"(xv.w - hw), "f"(xv.z - hz));
                const uint32_t off = row * PITCH + kseg * 8;
                asm volatile("st.shared.v2.b32 [%0], {%1,%2};"
                             :: "r"(hibase + off), "r"(h01), "r"(h23));
                asm volatile("st.shared.v2.b32 [%0], {%1,%2};"
                             :: "r"(lobase + off), "r"(l01), "r"(l23));
            }
            MBAR_ARRIVE(mf);   // release: stores above visible to consumers

            if (s + 1 < NSTAGE) {
                const int k0 = (s + 1) * KTILE;
                #pragma unroll
                for (int it = 0; it < 16; it++)
                    v[it] = *reinterpret_cast<const float4*>(
                        xb + (size_t)(it * 8 + gr) * MM + k0 + kseg * 4);
            }
        }

        // row sums: lanes sharing a row group reduce over k segments
        #pragma unroll
        for (int it = 0; it < 16; it++) {
            float vv = rs[it];
            vv += __shfl_xor_sync(0xffffffffu, vv, 4);
            vv += __shfl_xor_sync(0xffffffffu, vv, 2);
            vv += __shfl_xor_sync(0xffffffffu, vv, 1);
            if (kseg == 0)
                g_sum[ks * BB * CC + b * CC + it * 8 + gr] = vv;
        }
    }

    // ---- Q + Q^T fold via smem transpose (2 column-half phases) ------------
    __syncthreads();      // ring fully consumed; safe to overlay S
    {
        const int rw = (wid >> 1) * 32;
        const int cw = (wid & 1) * 64;
        #pragma unroll
        for (int h = 0; h < 2; h++) {
            if (wid < 8 && (wid & 1) == h) {
                #pragma unroll
                for (int mb = 0; mb < 2; mb++)
                    #pragma unroll
                    for (int jb = 0; jb < 8; jb++) {
                        const int row = rw + mb * 16 + g;
                        const int cl = jb * 8 + tg * 2;
                        sm.S[row][cl]         = accQ[mb][jb][0];
                        sm.S[row][cl + 1]     = accQ[mb][jb][1];
                        sm.S[row + 8][cl]     = accQ[mb][jb][2];
                        sm.S[row + 8][cl + 1] = accQ[mb][jb][3];
                    }
            }
            __syncthreads();
            if (wid < 8 && (wid >> 2) == h) {
                #pragma unroll
                for (int mb = 0; mb < 2; mb++)
                    #pragma unroll
                    for (int jb = 0; jb < 8; jb++) {
                        const int C = cw + jb * 8 + tg * 2;
                        const int R0 = (rw + mb * 16 + g) & 63;
                        accP[mb][jb][0] += sm.S[C][R0];
                        accP[mb][jb][1] += sm.S[C + 1][R0];
                        accP[mb][jb][2] += sm.S[C][R0 + 8];
                        accP[mb][jb][3] += sm.S[C + 1][R0 + 8];
                    }
            }
            __syncthreads();
        }

        // epilogue: write S = P + Q^T(accumulated) + Q
        if (wid < 8) {
            float* dst = g_part + (size_t)(ks * BB + b) * (CC * CC);
            #pragma unroll
            for (int mb = 0; mb < 2; mb++) {
                #pragma unroll
                for (int jb = 0; jb < 8; jb++) {
                    const int row = rw + mb * 16 + g;
                    const int col = cw + jb * 8 + tg * 2;
                    *reinterpret_cast<float2*>(&dst[(size_t)row * CC + col]) =
                        make_float2(accP[mb][jb][0] + accQ[mb][jb][0],
                                    accP[mb][jb][1] + accQ[mb][jb][1]);
                    *reinterpret_cast<float2*>(&dst[(size_t)(row + 8) * CC + col]) =
                        make_float2(accP[mb][jb][2] + accQ[mb][jb][2],
                                    accP[mb][jb][3] + accQ[mb][jb][3]);
                }
            }
        }
    }
}

// ---------------------------------------------------------------------------
// out[b][r][c] = (S0 + S1)/M - mu_r * mu_c
// ---------------------------------------------------------------------------
__global__ void __launch_bounds__(256) finalize(float* __restrict__ out) {
    const int i = blockIdx.x * blockDim.x + threadIdx.x;    // float4 index
    const int base = i * 4;
    const int b = base >> 14;
    const int r = (base >> 7) & (CC - 1);
    const int c = base & (CC - 1);
    const float inv = 1.0f / (float)MM;

    const float4 s0 = reinterpret_cast<const float4*>(g_part)[i];
    const float4 s1 = reinterpret_cast<const float4*>(g_part)[BB * CC * CC / 4 + i];

    const float mur = (g_sum[b * CC + r] + g_sum[BB * CC + b * CC + r]) * inv;
    const float mc0 = (g_sum[b * CC + c + 0] + g_sum[BB * CC + b * CC + c + 0]) * inv;
    const float mc1 = (g_sum[b * CC + c + 1] + g_sum[BB * CC + b * CC + c + 1]) * inv;
    const float mc2 = (g_sum[b * CC + c + 2] + g_sum[BB * CC + b * CC + c + 2]) * inv;
    const float mc3 = (g_sum[b * CC + c + 3] + g_sum[BB * CC + b * CC + c + 3]) * inv;

    float4 o;
    o.x = (s0.x + s1.x) * inv - mur * mc0;
    o.y = (s0.y + s1.y) * inv - mur * mc1;
    o.z = (s0.z + s1.z) * inv - mur * mc2;
    o.w = (s0.w + s1.w) * inv - mur * mc3;
    reinterpret_cast<float4*>(out)[i] = o;
}

// ---------------------------------------------------------------------------
extern "C" void kernel_launch(void* const* d_in, const int* in_sizes, int n_in,
                              void* d_out, int out_size) {
    const float* x = (const float*)d_in[0];
    float* out = (float*)d_out;

    dim3 grid(KS, BB);
    syrk_mma<<<grid, NTHREADS>>>(x);
    finalize<<<(BB * CC * CC / 4) / 256, 256>>>(out);
}

// round 10
// speedup vs baseline: 1.3188x; 1.3188x over previous
#include <cuda_runtime.h>
#include <cstdint>

// Problem constants: B=64, C=128, M=H*W=4096, fp32 in/out
#define BB 64
#define CC 128
#define MM 4096
#define KS 2                    // split-K across CTAs
#define KCHUNK (MM / KS)        // 2048
#define KTILE 64                // bf16 k per stage
#define NSTAGE (KCHUNK / KTILE) // 32
#define PITCH 144               // smem row pitch bytes (128B data + 16B pad)
#define TILEB (CC * PITCH)      // 18432 bytes per bf16 tile
#define SPITCH 72               // transpose buffer pitch (floats)
#define SMEM_BYTES (4 * TILEB)  // 73728: 2 bufs x (hi+lo); S overlay fits inside

// ---------------- scratch (__device__ globals; no allocs allowed) ----------
__device__ float g_sum[KS * BB * CC];            // per-(ks,b,c) row sums
__device__ float g_part[KS * BB * CC * CC];      // per-ks S = P + Q + Q^T

// ---------------- helpers ---------------------------------------------------
__device__ __forceinline__ uint32_t smem_u32(const void* p) {
    uint32_t a;
    asm("{ .reg .u64 t; cvta.to.shared.u64 t, %1; cvt.u32.u64 %0, t; }"
        : "=r"(a) : "l"(p));
    return a;
}
__device__ __forceinline__ void ldsm_x4(uint32_t& r0, uint32_t& r1,
                                        uint32_t& r2, uint32_t& r3, uint32_t a) {
    asm volatile("ldmatrix.sync.aligned.m8n8.x4.shared.b16 {%0,%1,%2,%3}, [%4];"
                 : "=r"(r0), "=r"(r1), "=r"(r2), "=r"(r3) : "r"(a));
}
__device__ __forceinline__ void mma_bf16(float* d, const uint32_t* a,
                                         uint32_t b0, uint32_t b1) {
    asm volatile(
        "mma.sync.aligned.m16n8k16.row.col.f32.bf16.bf16.f32 "
        "{%0,%1,%2,%3}, {%4,%5,%6,%7}, {%8,%9}, {%0,%1,%2,%3};"
        : "+f"(d[0]), "+f"(d[1]), "+f"(d[2]), "+f"(d[3])
        : "r"(a[0]), "r"(a[1]), "r"(a[2]), "r"(a[3]), "r"(b0), "r"(b1));
}

// ---------------------------------------------------------------------------
// SYRK via bf16-split mma.sync, two-term (P = hi*hi^T, Q = hi*lo^T), with the
// Q + Q^T fold done in-CTA through an smem transpose. grid = (KS, BB).
// ---------------------------------------------------------------------------
__global__ void __launch_bounds__(256, 1) syrk_mma(const float* __restrict__ x) {
    extern __shared__ __align__(128) uint8_t smraw[];
    uint8_t (*tiles)[2 * TILEB] = reinterpret_cast<uint8_t (*)[2 * TILEB]>(smraw);
    float (*S)[SPITCH] = reinterpret_cast<float (*)[SPITCH]>(smraw);

    const int tid = threadIdx.x;
    const int wid = tid >> 5;
    const int lid = tid & 31;
    const int b = blockIdx.y;
    const int ks = blockIdx.x;
    const float* xb = x + (size_t)b * CC * MM + ks * KCHUNK;

    const int rw = (wid >> 1) * 32;   // warp row base in 128x128 output
    const int cw = (wid & 1) * 64;    // warp col base

    float accP[2][8][4], accQ[2][8][4];
    #pragma unroll
    for (int mb = 0; mb < 2; mb++)
        #pragma unroll
        for (int jb = 0; jb < 8; jb++)
            #pragma unroll
            for (int q = 0; q < 4; q++) { accP[mb][jb][q] = 0.0f; accQ[mb][jb][q] = 0.0f; }

    float rs[8];
    #pragma unroll
    for (int i = 0; i < 8; i++) rs[i] = 0.f;

    // loader mapping: 16 k-segments (float4) per row, 16 row groups of 8 rows
    const int rowg = tid >> 4;        // 0..15
    const int kseg = tid & 15;        // 0..15

    // ldmatrix lane byte-offsets inside a tile
    const uint32_t a_row_off = ((lid & 7) + ((lid >> 3) & 1) * 8) * PITCH
                             + ((lid >> 4) * 8) * 2;
    const uint32_t b4_row_off = ((lid & 7) + (lid >> 4) * 8) * PITCH
                              + (((lid >> 3) & 1) * 8) * 2;

    float4 v[8];
    #pragma unroll
    for (int it = 0; it < 8; it++)
        v[it] = *reinterpret_cast<const float4*>(
            xb + (size_t)(it * 16 + rowg) * MM + kseg * 4);

    for (int s = 0; s < NSTAGE; s++) {
        const int buf = s & 1;
        const uint32_t hibase = smem_u32(&tiles[buf][0]);
        const uint32_t lobase = hibase + TILEB;

        // convert current regs -> smem tiles, accumulate row sums
        #pragma unroll
        for (int it = 0; it < 8; it++) {
            const int row = it * 16 + rowg;
            const float4 xv = v[it];
            rs[it] += (xv.x + xv.y) + (xv.z + xv.w);
            uint32_t h01, h23, l01, l23;
            asm("cvt.rn.bf16x2.f32 %0, %1, %2;" : "=r"(h01) : "f"(xv.y), "f"(xv.x));
            asm("cvt.rn.bf16x2.f32 %0, %1, %2;" : "=r"(h23) : "f"(xv.w), "f"(xv.z));
            const float hx = __uint_as_float(h01 << 16);
            const float hy = __uint_as_float(h01 & 0xffff0000u);
            const float hz = __uint_as_float(h23 << 16);
            const float hw = __uint_as_float(h23 & 0xffff0000u);
            asm("cvt.rn.bf16x2.f32 %0, %1, %2;" : "=r"(l01) : "f"(xv.y - hy), "f"(xv.x - hx));
            asm("cvt.rn.bf16x2.f32 %0, %1, %2;" : "=r"(l23) : "f"(xv.w - hw), "f"(xv.z - hz));
            const uint32_t off = row * PITCH + kseg * 8;
            asm volatile("st.shared.v2.b32 [%0], {%1,%2};"
                         :: "r"(hibase + off), "r"(h01), "r"(h23));
            asm volatile("st.shared.v2.b32 [%0], {%1,%2};"
                         :: "r"(lobase + off), "r"(l01), "r"(l23));
        }
        // Single barrier per stage (double buffering covers the WAR hazard).
        __syncthreads();

        // issue next stage's global loads now: a full stage of latency cover
        if (s + 1 < NSTAGE) {
            const int k0 = (s + 1) * KTILE;
            #pragma unroll
            for (int it = 0; it < 8; it++)
                v[it] = *reinterpret_cast<const float4*>(
                    xb + (size_t)(it * 16 + rowg) * MM + k0 + kseg * 4);
        }

        // compute: 4 k16 steps; A is always hi; B fragments via x4 (n16 each)
        #pragma unroll
        for (int kb = 0; kb < 4; kb++) {
            uint32_t ah[2][4];
            #pragma unroll
            for (int mb = 0; mb < 2; mb++) {
                const uint32_t aoff = (rw + mb * 16) * PITCH + kb * 32 + a_row_off;
                ldsm_x4(ah[mb][0], ah[mb][1], ah[mb][2], ah[mb][3], hibase + aoff);
            }
            #pragma unroll
            for (int jbp = 0; jbp < 4; jbp++) {
                const uint32_t boff = (cw + jbp * 16) * PITCH + kb * 32 + b4_row_off;
                uint32_t bh0, bh1, bh2, bh3, bl0, bl1, bl2, bl3;
                ldsm_x4(bh0, bh1, bh2, bh3, hibase + boff);
                ldsm_x4(bl0, bl1, bl2, bl3, lobase + boff);
                #pragma unroll
                for (int mb = 0; mb < 2; mb++) {
                    mma_bf16(accP[mb][2 * jbp + 0], ah[mb], bh0, bh1);
                    mma_bf16(accP[mb][2 * jbp + 1], ah[mb], bh2, bh3);
                    mma_bf16(accQ[mb][2 * jbp + 0], ah[mb], bl0, bl1);
                    mma_bf16(accQ[mb][2 * jbp + 1], ah[mb], bl2, bl3);
                }
            }
        }
    }

    // row sums: 16 lanes (same rowg) share a row; reduce over kseg, store per ks
    #pragma unroll
    for (int it = 0; it < 8; it++) {
        float vv = rs[it];
        vv += __shfl_xor_sync(0xffffffffu, vv, 8);
        vv += __shfl_xor_sync(0xffffffffu, vv, 4);
        vv += __shfl_xor_sync(0xffffffffu, vv, 2);
        vv += __shfl_xor_sync(0xffffffffu, vv, 1);
        if (kseg == 0)
            g_sum[ks * BB * CC + b * CC + it * 16 + rowg] = vv;
    }

    // ---- Q + Q^T fold via smem transpose (2 column-half phases) ------------
    const int g = lid >> 2;            // 0..7
    const int tg = lid & 3;            // 0..3
    __syncthreads();                   // last-stage ldsm done before S overlay
    #pragma unroll
    for (int h = 0; h < 2; h++) {
        // producers: warps whose column half == h store their accQ
        if ((wid & 1) == h) {
            #pragma unroll
            for (int mb = 0; mb < 2; mb++)
                #pragma unroll
                for (int jb = 0; jb < 8; jb++) {
                    const int row = rw + mb * 16 + g;
                    const int cl = jb * 8 + tg * 2;
                    S[row][cl]         = accQ[mb][jb][0];
                    S[row][cl + 1]     = accQ[mb][jb][1];
                    S[row + 8][cl]     = accQ[mb][jb][2];
                    S[row + 8][cl + 1] = accQ[mb][jb][3];
                }
        }
        __syncthreads();
        // consumers: warps whose rows lie in [h*64, h*64+64) add Q^T
        if ((wid >> 2) == h) {
            #pragma unroll
            for (int mb = 0; mb < 2; mb++)
                #pragma unroll
                for (int jb = 0; jb < 8; jb++) {
                    const int C = cw + jb * 8 + tg * 2;
                    const int R0 = (rw + mb * 16 + g) & 63;
                    accP[mb][jb][0] += S[C][R0];
                    accP[mb][jb][1] += S[C + 1][R0];
                    accP[mb][jb][2] += S[C][R0 + 8];
                    accP[mb][jb][3] += S[C + 1][R0 + 8];
                }
        }
        __syncthreads();
    }

    // epilogue: write S = P + Q^T(accumulated) + Q
    float* dst = g_part + (size_t)(ks * BB + b) * (CC * CC);
    #pragma unroll
    for (int mb = 0; mb < 2; mb++) {
        #pragma unroll
        for (int jb = 0; jb < 8; jb++) {
            const int row = rw + mb * 16 + g;
            const int col = cw + jb * 8 + tg * 2;
            *reinterpret_cast<float2*>(&dst[(size_t)row * CC + col]) =
                make_float2(accP[mb][jb][0] + accQ[mb][jb][0],
                            accP[mb][jb][1] + accQ[mb][jb][1]);
            *reinterpret_cast<float2*>(&dst[(size_t)(row + 8) * CC + col]) =
                make_float2(accP[mb][jb][2] + accQ[mb][jb][2],
                            accP[mb][jb][3] + accQ[mb][jb][3]);
        }
    }
}

// ---------------------------------------------------------------------------
// out[b][r][c] = (S0 + S1)/M - mu_r * mu_c
// ---------------------------------------------------------------------------
__global__ void __launch_bounds__(256) finalize(float* __restrict__ out) {
    const int i = blockIdx.x * blockDim.x + threadIdx.x;    // float4 index
    const int base = i * 4;
    const int b = base >> 14;
    const int r = (base >> 7) & (CC - 1);
    const int c = base & (CC - 1);
    const float inv = 1.0f / (float)MM;

    const float4 s0 = reinterpret_cast<const float4*>(g_part)[i];
    const float4 s1 = reinterpret_cast<const float4*>(g_part)[BB * CC * CC / 4 + i];

    const float mur = (g_sum[b * CC + r] + g_sum[BB * CC + b * CC + r]) * inv;
    const float mc0 = (g_sum[b * CC + c + 0] + g_sum[BB * CC + b * CC + c + 0]) * inv;
    const float mc1 = (g_sum[b * CC + c + 1] + g_sum[BB * CC + b * CC + c + 1]) * inv;
    const float mc2 = (g_sum[b * CC + c + 2] + g_sum[BB * CC + b * CC + c + 2]) * inv;
    const float mc3 = (g_sum[b * CC + c + 3] + g_sum[BB * CC + b * CC + c + 3]) * inv;

    float4 o;
    o.x = (s0.x + s1.x) * inv - mur * mc0;
    o.y = (s0.y + s1.y) * inv - mur * mc1;
    o.z = (s0.z + s1.z) * inv - mur * mc2;
    o.w = (s0.w + s1.w) * inv - mur * mc3;
    reinterpret_cast<float4*>(out)[i] = o;
}

// ---------------------------------------------------------------------------
extern "C" void kernel_launch(void* const* d_in, const int* in_sizes, int n_in,
                              void* d_out, int out_size) {
    const float* x = (const float*)d_in[0];
    float* out = (float*)d_out;

    cudaFuncSetAttribute(syrk_mma, cudaFuncAttributeMaxDynamicSharedMemorySize,
                         SMEM_BYTES);

    dim3 grid(KS, BB);
    syrk_mma<<<grid, 256, SMEM_BYTES>>>(x);
    finalize<<<(BB * CC * CC / 4) / 256, 256>>>(out);
}